// round 6
// baseline (speedup 1.0000x reference)
#include <cuda_runtime.h>
#include <math.h>
#include <stdint.h>

#define B_  2
#define L_  8192
#define H_  16
#define D_  64
#define C_  1024
#define BK  64
#define NT  256
#define LOG2E 1.4426950408889634f

__device__ float g_cos[L_ * 32];
__device__ float g_sin[L_ * 32];

// fragment-ready scratch: 4 x 32 MB (u64 units)
__device__ uint64_t g_KfH[4194304];
__device__ uint64_t g_KfL[4194304];
__device__ uint64_t g_VfH[4194304];
__device__ uint64_t g_VfL[4194304];

__global__ void rope_table_k(const int* __restrict__ startp) {
    int i = blockIdx.x * blockDim.x + threadIdx.x;
    if (i >= L_ * 32) return;
    int pos = *startp + (i >> 5);
    int j = i & 31;
    float invf = (float)(1.0 / pow(10000.0, (double)j / 32.0));
    float ang  = (float)pos * invf;
    g_cos[i] = (float)cos((double)ang);
    g_sin[i] = (float)sin((double)ang);
}

// ---------------- helpers ----------------
__device__ __forceinline__ uint32_t prmt_hi(uint32_t a, uint32_t b) {
    uint32_t r; asm("prmt.b32 %0, %1, %2, 0x7632;" : "=r"(r) : "r"(a), "r"(b)); return r;
}
__device__ __forceinline__ uint32_t bfh(float v) {   // bf16 RNE bits (high 16)
    uint32_t u = __float_as_uint(v);
    return u + 0x7FFFu + ((u >> 16) & 1u);
}
__device__ __forceinline__ float ex2f(float x) {
    float y; asm("ex2.approx.ftz.f32 %0, %1;" : "=f"(y) : "f"(x)); return y;
}
__device__ __forceinline__ void ldg64(uint32_t& x, uint32_t& y, const uint64_t* p) {
    asm volatile("ld.global.nc.v2.b32 {%0,%1}, [%2];" : "=r"(x), "=r"(y) : "l"(p));
}
__device__ __forceinline__ void mma_bf16(float* c, const uint32_t* a, uint32_t b0, uint32_t b1) {
    asm volatile(
        "mma.sync.aligned.m16n8k16.row.col.f32.bf16.bf16.f32 "
        "{%0,%1,%2,%3}, {%4,%5,%6,%7}, {%8,%9}, {%0,%1,%2,%3};"
        : "+f"(c[0]), "+f"(c[1]), "+f"(c[2]), "+f"(c[3])
        : "r"(a[0]), "r"(a[1]), "r"(a[2]), "r"(a[3]), "r"(b0), "r"(b1));
}
__device__ __forceinline__ void pack_hilo(float x0, float x1, uint32_t& hi, uint32_t& lo) {
    uint32_t h0 = bfh(x0), h1 = bfh(x1);
    hi = prmt_hi(h0, h1);
    float r0 = x0 - __uint_as_float(h0 & 0xFFFF0000u);
    float r1 = x1 - __uint_as_float(h1 & 0xFFFF0000u);
    lo = prmt_hi(bfh(r0), bfh(r1));
}

// ---------------- prep: K -> RoPE'd bf16 hi/lo fragments ----------------
// thread g: lb=g&3, la=(g>>2)&7, t01=(g>>5)&1, m=(g>>6)&1023, sc=g>>16
// writes planes t01 (d<32 half) and t01+2 (d>=32 half)
__global__ void prep_k(const float* __restrict__ k) {
    uint32_t g = blockIdx.x * blockDim.x + threadIdx.x;
    int lb = g & 3, la = (g >> 2) & 7, t01 = (g >> 5) & 1, m = (g >> 6) & 1023;
    int sc = g >> 16;
    int b = sc >> 4, h = sc & 15;
    int l = 8 * m + la;
    const float* gk = k + (((long)b * L_ + l) * H_ + h) * D_;
    int d0 = 16 * t01 + 2 * lb;
    float2 x0 = *(const float2*)(gk + d0);
    float2 x1 = *(const float2*)(gk + d0 + 8);
    float2 y0 = *(const float2*)(gk + d0 + 32);
    float2 y1 = *(const float2*)(gk + d0 + 40);
    float2 c0 = *(const float2*)(g_cos + l * 32 + d0);
    float2 c1 = *(const float2*)(g_cos + l * 32 + d0 + 8);
    float2 s0 = *(const float2*)(g_sin + l * 32 + d0);
    float2 s1 = *(const float2*)(g_sin + l * 32 + d0 + 8);
    // low half (d0..): x*c - y*s ; high half (d0+32): y*c + x*s
    uint32_t hA, lA, hB, lB;
    pack_hilo(x0.x*c0.x - y0.x*s0.x, x0.y*c0.y - y0.y*s0.y, hA, lA);
    pack_hilo(x1.x*c1.x - y1.x*s1.x, x1.y*c1.y - y1.y*s1.y, hB, lB);
    uint64_t loHi = (uint64_t)hA | ((uint64_t)hB << 32);
    uint64_t loLo = (uint64_t)lA | ((uint64_t)lB << 32);
    pack_hilo(y0.x*c0.x + x0.x*s0.x, y0.y*c0.y + x0.y*s0.y, hA, lA);
    pack_hilo(y1.x*c1.x + x1.x*s1.x, y1.y*c1.y + x1.y*s1.y, hB, lB);
    uint64_t hiHi = (uint64_t)hA | ((uint64_t)hB << 32);
    uint64_t hiLo = (uint64_t)lA | ((uint64_t)lB << 32);
    uint32_t base = ((uint32_t)sc * 1024 + m) * 128 + la * 4 + lb;
    g_KfH[base + t01 * 32]       = loHi;
    g_KfL[base + t01 * 32]       = loLo;
    g_KfH[base + (t01 + 2) * 32] = hiHi;
    g_KfL[base + (t01 + 2) * 32] = hiLo;
}

// ---------------- prep: V -> transposed bf16 hi/lo fragments ----------------
// thread g: lb=g&3, d=(g>>2)&63, t2=(g>>8)&3, gt=(g>>10)&127, sc=g>>17
__global__ void prep_v(const float* __restrict__ v) {
    uint32_t g = blockIdx.x * blockDim.x + threadIdx.x;
    int lb = g & 3, d = (g >> 2) & 63, t2 = (g >> 8) & 3, gt = (g >> 10) & 127;
    int sc = g >> 17;
    int b = sc >> 4, h = sc & 15;
    int l0 = gt * 64 + t2 * 16 + 2 * lb;
    const float* gv = v + (((long)b * L_ + l0) * H_ + h) * D_ + d;
    const int str = H_ * D_;
    float v0 = gv[0], v1 = gv[str], v8 = gv[8 * str], v9 = gv[9 * str];
    uint32_t h0, l0b, h8, l8;
    pack_hilo(v0, v1, h0, l0b);
    pack_hilo(v8, v9, h8, l8);
    uint32_t idx = ((uint32_t)sc * 128 + gt) * 1024 + t2 * 256 + d * 4 + lb;
    g_VfH[idx] = (uint64_t)h0  | ((uint64_t)h8 << 32);
    g_VfL[idx] = (uint64_t)l0b | ((uint64_t)l8 << 32);
}

// ---------------- main: flash attention, fragments direct from gmem ----------------
__global__ void __launch_bounds__(NT, 2)
attn_k(const float* __restrict__ q, float* __restrict__ out) {
    const int tid = threadIdx.x, w = tid >> 5, lane = tid & 31;
    const int qt = 7 - blockIdx.x;            // heavy CTAs first
    const int n  = blockIdx.y >> 4, h = blockIdx.y & 15, b = blockIdx.z;
    const int sc = b * 16 + h;
    const int qbase = qt * 128;
    const int la = lane >> 2, lb = lane & 3;

    // ---------- Q: load + RoPE(+log2e) + bf16 split -> A fragments ----------
    uint32_t Qhi[4][4], Qlo[4][4];
    {
        const int bq = lb * 2;
        float rot[2][4][4];
        #pragma unroll
        for (int r = 0; r < 2; r++) {
            int m  = 16 * w + la + 8 * r;
            int lq = n * C_ + qbase + m;
            const float* gq = q + (((long)b * L_ + lq) * H_ + h) * D_;
            const float* gc = g_cos + lq * 32;
            const float* gs = g_sin + lq * 32;
            float xv[4][4], cs[2][4], sn[2][4];
            #pragma unroll
            for (int t = 0; t < 4; t++) {
                float2 u0 = *(const float2*)(gq + 16 * t + bq);
                float2 u1 = *(const float2*)(gq + 16 * t + bq + 8);
                xv[t][0] = u0.x; xv[t][1] = u0.y; xv[t][2] = u1.x; xv[t][3] = u1.y;
            }
            #pragma unroll
            for (int t = 0; t < 2; t++) {
                float2 c0 = *(const float2*)(gc + 16 * t + bq);
                float2 c1 = *(const float2*)(gc + 16 * t + bq + 8);
                cs[t][0] = c0.x; cs[t][1] = c0.y; cs[t][2] = c1.x; cs[t][3] = c1.y;
                float2 s0 = *(const float2*)(gs + 16 * t + bq);
                float2 s1 = *(const float2*)(gs + 16 * t + bq + 8);
                sn[t][0] = s0.x; sn[t][1] = s0.y; sn[t][2] = s1.x; sn[t][3] = s1.y;
            }
            #pragma unroll
            for (int t = 0; t < 2; t++)
                #pragma unroll
                for (int i = 0; i < 4; i++) {
                    rot[r][t][i]   = (xv[t][i] * cs[t][i] - xv[t+2][i] * sn[t][i]) * LOG2E;
                    rot[r][t+2][i] = (xv[t+2][i] * cs[t][i] + xv[t][i] * sn[t][i]) * LOG2E;
                }
        }
        #pragma unroll
        for (int t = 0; t < 4; t++) {
            pack_hilo(rot[0][t][0], rot[0][t][1], Qhi[t][0], Qlo[t][0]);
            pack_hilo(rot[1][t][0], rot[1][t][1], Qhi[t][1], Qlo[t][1]);
            pack_hilo(rot[0][t][2], rot[0][t][3], Qhi[t][2], Qlo[t][2]);
            pack_hilo(rot[1][t][2], rot[1][t][3], Qhi[t][3], Qlo[t][3]);
        }
    }

    float o[8][4];
    #pragma unroll
    for (int j = 0; j < 8; j++)
        #pragma unroll
        for (int i = 0; i < 4; i++) o[j][i] = 0.f;
    float lsum0 = 0.f, lsum1 = 0.f;

    const int row0 = qbase + 16 * w + la;
    const int row1 = row0 + 8;
    const int nkt = 2 * qt + 2;

    // fragment base pointers (per-lane)
    const uint64_t* pKH = g_KfH + ((uint32_t)sc * 1024 + n * 128) * 128 + la * 4 + lb;
    const uint64_t* pKL = g_KfL + ((uint32_t)sc * 1024 + n * 128) * 128 + la * 4 + lb;
    const uint64_t* pVH = g_VfH + ((uint32_t)sc * 128 + n * 16) * 1024 + la * 4 + lb;
    const uint64_t* pVL = g_VfL + ((uint32_t)sc * 128 + n * 16) * 1024 + la * 4 + lb;

    for (int kt = 0; kt < nkt; kt++) {
        const int kbase = kt * BK;
        const uint32_t ko = (uint32_t)kt * 1024;

        // ---------- S = Q @ K^T (3-pass split), B frags straight from gmem ----------
        float c[8][4];
        #pragma unroll
        for (int j = 0; j < 8; j++)
            #pragma unroll
            for (int i = 0; i < 4; i++) c[j][i] = 0.f;

        #pragma unroll
        for (int t = 0; t < 4; t++) {
            #pragma unroll
            for (int j = 0; j < 8; j++) {
                uint32_t off = ko + (uint32_t)j * 128 + (uint32_t)t * 32;
                uint32_t bh0, bh1, bl0, bl1;
                ldg64(bh0, bh1, pKH + off);
                ldg64(bl0, bl1, pKL + off);
                mma_bf16(c[j], Qhi[t], bh0, bh1);
                mma_bf16(c[j], Qlo[t], bh0, bh1);
                mma_bf16(c[j], Qhi[t], bl0, bl1);
            }
        }

        // ---------- mask + exp2 + repack P into A-fragments (registers only) ----------
        uint32_t Phi[4][4], Plo[4][4];
        #pragma unroll
        for (int j = 0; j < 8; j++) {
            int col = kbase + 8 * j + lb * 2;
            float p0 = (col     > row0) ? 0.f : ex2f(c[j][0]);
            float p1 = (col + 1 > row0) ? 0.f : ex2f(c[j][1]);
            float p2 = (col     > row1) ? 0.f : ex2f(c[j][2]);
            float p3 = (col + 1 > row1) ? 0.f : ex2f(c[j][3]);
            lsum0 += p0 + p1; lsum1 += p2 + p3;
            int t = j >> 1, off = (j & 1) ? 2 : 0;
            pack_hilo(p0, p1, Phi[t][off],     Plo[t][off]);
            pack_hilo(p2, p3, Phi[t][off + 1], Plo[t][off + 1]);
        }

        // ---------- O += P @ V (3-pass split) ----------
        #pragma unroll
        for (int t = 0; t < 4; t++) {
            #pragma unroll
            for (int j = 0; j < 8; j++) {
                uint32_t off = ko + (uint32_t)t * 256 + (uint32_t)j * 32;
                uint32_t bh0, bh1, bl0, bl1;
                ldg64(bh0, bh1, pVH + off);
                ldg64(bl0, bl1, pVL + off);
                mma_bf16(o[j], Phi[t], bh0, bh1);
                mma_bf16(o[j], Plo[t], bh0, bh1);
                mma_bf16(o[j], Phi[t], bl0, bl1);
            }
        }
    }

    // ---------- normalize + store ----------
    lsum0 += __shfl_xor_sync(0xffffffffu, lsum0, 1);
    lsum0 += __shfl_xor_sync(0xffffffffu, lsum0, 2);
    lsum1 += __shfl_xor_sync(0xffffffffu, lsum1, 1);
    lsum1 += __shfl_xor_sync(0xffffffffu, lsum1, 2);
    float inv0 = 1.0f / lsum0, inv1 = 1.0f / lsum1;

    const int lq0 = n * C_ + row0, lq1 = n * C_ + row1;
    float* g0 = out + (((long)b * L_ + lq0) * H_ + h) * D_;
    float* g1 = out + (((long)b * L_ + lq1) * H_ + h) * D_;
    #pragma unroll
    for (int j = 0; j < 8; j++) {
        int d = 8 * j + lb * 2;
        *(float2*)(g0 + d) = make_float2(o[j][0] * inv0, o[j][1] * inv0);
        *(float2*)(g1 + d) = make_float2(o[j][2] * inv1, o[j][3] * inv1);
    }
}

extern "C" void kernel_launch(void* const* d_in, const int* in_sizes, int n_in,
                              void* d_out, int out_size) {
    const float* q = (const float*)d_in[0];
    const float* k = (const float*)d_in[1];
    const float* v = (const float*)d_in[2];
    const int* st  = (const int*)d_in[3];
    float* out     = (float*)d_out;

    rope_table_k<<<(L_ * 32 + 255) / 256, 256>>>(st);
    prep_k<<<8192, 256>>>(k);
    prep_v<<<16384, 256>>>(v);
    attn_k<<<dim3(8, (L_ / C_) * H_, B_), NT>>>(q, out);
}

// round 7
// speedup vs baseline: 1.8647x; 1.8647x over previous
#include <cuda_runtime.h>
#include <math.h>
#include <stdint.h>

#define B_  2
#define L_  8192
#define H_  16
#define D_  64
#define C_  1024
#define BK  64
#define LOG2E 1.4426950408889634f

__device__ float g_cos[L_ * 32];
__device__ float g_sin[L_ * 32];

// fragment-ready scratch: 4 x 32 MB (u64 units)
__device__ uint64_t g_KfH[4194304];
__device__ uint64_t g_KfL[4194304];
__device__ uint64_t g_VfH[4194304];
__device__ uint64_t g_VfL[4194304];

__global__ void rope_table_k(const int* __restrict__ startp) {
    int i = blockIdx.x * blockDim.x + threadIdx.x;
    if (i >= L_ * 32) return;
    int pos = *startp + (i >> 5);
    int j = i & 31;
    float invf = (float)(1.0 / pow(10000.0, (double)j / 32.0));
    float ang  = (float)pos * invf;
    g_cos[i] = (float)cos((double)ang);
    g_sin[i] = (float)sin((double)ang);
}

// ---------------- helpers ----------------
__device__ __forceinline__ uint32_t smem_u32(const void* p) {
    uint32_t a;
    asm("{ .reg .u64 t; cvta.to.shared.u64 t, %1; cvt.u32.u64 %0, t; }" : "=r"(a) : "l"(p));
    return a;
}
__device__ __forceinline__ uint32_t prmt_hi(uint32_t a, uint32_t b) {
    uint32_t r; asm("prmt.b32 %0, %1, %2, 0x7632;" : "=r"(r) : "r"(a), "r"(b)); return r;
}
__device__ __forceinline__ uint32_t bfh(float v) {
    uint32_t u = __float_as_uint(v);
    return u + 0x7FFFu + ((u >> 16) & 1u);
}
__device__ __forceinline__ float ex2f(float x) {
    float y; asm("ex2.approx.ftz.f32 %0, %1;" : "=f"(y) : "f"(x)); return y;
}
__device__ __forceinline__ void lds64(uint32_t& x, uint32_t& y, uint32_t a) {
    asm volatile("ld.shared.v2.b32 {%0,%1}, [%2];" : "=r"(x), "=r"(y) : "r"(a));
}
__device__ __forceinline__ void cpa16(uint32_t s, const uint64_t* g) {
    asm volatile("cp.async.cg.shared.global [%0], [%1], 16;" :: "r"(s), "l"(g));
}
#define CP_COMMIT() asm volatile("cp.async.commit_group;" ::: "memory")
#define CP_WAIT0()  asm volatile("cp.async.wait_group 0;" ::: "memory")
__device__ __forceinline__ void mma_bf16(float* c, const uint32_t* a, uint32_t b0, uint32_t b1) {
    asm volatile(
        "mma.sync.aligned.m16n8k16.row.col.f32.bf16.bf16.f32 "
        "{%0,%1,%2,%3}, {%4,%5,%6,%7}, {%8,%9}, {%0,%1,%2,%3};"
        : "+f"(c[0]), "+f"(c[1]), "+f"(c[2]), "+f"(c[3])
        : "r"(a[0]), "r"(a[1]), "r"(a[2]), "r"(a[3]), "r"(b0), "r"(b1));
}
__device__ __forceinline__ void pack_hilo(float x0, float x1, uint32_t& hi, uint32_t& lo) {
    uint32_t h0 = bfh(x0), h1 = bfh(x1);
    hi = prmt_hi(h0, h1);
    float r0 = x0 - __uint_as_float(h0 & 0xFFFF0000u);
    float r1 = x1 - __uint_as_float(h1 & 0xFFFF0000u);
    lo = prmt_hi(bfh(r0), bfh(r1));
}

// ---------------- prep: K -> RoPE'd bf16 hi/lo fragments ----------------
__global__ void prep_k(const float* __restrict__ k) {
    uint32_t g = blockIdx.x * blockDim.x + threadIdx.x;
    int lb = g & 3, la = (g >> 2) & 7, t01 = (g >> 5) & 1, m = (g >> 6) & 1023;
    int sc = g >> 16;
    int b = sc >> 4, h = sc & 15;
    int l = 8 * m + la;
    const float* gk = k + (((long)b * L_ + l) * H_ + h) * D_;
    int d0 = 16 * t01 + 2 * lb;
    float2 x0 = *(const float2*)(gk + d0);
    float2 x1 = *(const float2*)(gk + d0 + 8);
    float2 y0 = *(const float2*)(gk + d0 + 32);
    float2 y1 = *(const float2*)(gk + d0 + 40);
    float2 c0 = *(const float2*)(g_cos + l * 32 + d0);
    float2 c1 = *(const float2*)(g_cos + l * 32 + d0 + 8);
    float2 s0 = *(const float2*)(g_sin + l * 32 + d0);
    float2 s1 = *(const float2*)(g_sin + l * 32 + d0 + 8);
    uint32_t hA, lA, hB, lB;
    pack_hilo(x0.x*c0.x - y0.x*s0.x, x0.y*c0.y - y0.y*s0.y, hA, lA);
    pack_hilo(x1.x*c1.x - y1.x*s1.x, x1.y*c1.y - y1.y*s1.y, hB, lB);
    uint64_t loHi = (uint64_t)hA | ((uint64_t)hB << 32);
    uint64_t loLo = (uint64_t)lA | ((uint64_t)lB << 32);
    pack_hilo(y0.x*c0.x + x0.x*s0.x, y0.y*c0.y + x0.y*s0.y, hA, lA);
    pack_hilo(y1.x*c1.x + x1.x*s1.x, y1.y*c1.y + x1.y*s1.y, hB, lB);
    uint64_t hiHi = (uint64_t)hA | ((uint64_t)hB << 32);
    uint64_t hiLo = (uint64_t)lA | ((uint64_t)lB << 32);
    uint32_t base = ((uint32_t)sc * 1024 + m) * 128 + la * 4 + lb;
    g_KfH[base + t01 * 32]       = loHi;
    g_KfL[base + t01 * 32]       = loLo;
    g_KfH[base + (t01 + 2) * 32] = hiHi;
    g_KfL[base + (t01 + 2) * 32] = hiLo;
}

// ---------------- prep: V -> transposed bf16 hi/lo fragments ----------------
__global__ void prep_v(const float* __restrict__ v) {
    uint32_t g = blockIdx.x * blockDim.x + threadIdx.x;
    int lb = g & 3, d = (g >> 2) & 63, t2 = (g >> 8) & 3, gt = (g >> 10) & 127;
    int sc = g >> 17;
    int b = sc >> 4, h = sc & 15;
    int l0 = gt * 64 + t2 * 16 + 2 * lb;
    const float* gv = v + (((long)b * L_ + l0) * H_ + h) * D_ + d;
    const int str = H_ * D_;
    float v0 = gv[0], v1 = gv[str], v8 = gv[8 * str], v9 = gv[9 * str];
    uint32_t h0, l0b, h8, l8;
    pack_hilo(v0, v1, h0, l0b);
    pack_hilo(v8, v9, h8, l8);
    uint32_t idx = ((uint32_t)sc * 128 + gt) * 1024 + t2 * 256 + d * 4 + lb;
    g_VfH[idx] = (uint64_t)h0  | ((uint64_t)h8 << 32);
    g_VfL[idx] = (uint64_t)l0b | ((uint64_t)l8 << 32);
}

// smem per buffer: KH 8KB | KL 8KB | VH 8KB | VL 8KB = 32KB; double buffered = 64KB
#define BUFB 32768
#define P_KH 0
#define P_KL 8192
#define P_VH 16384
#define P_VL 24576

// ---------------- main: 4 warps, M=32/warp, cp.async double-buffered tiles ----------------
__global__ void __launch_bounds__(128, 2)
attn_k(const float* __restrict__ q, float* __restrict__ out) {
    extern __shared__ __align__(16) char smc[];
    const uint32_t sb = smem_u32(smc);
    const int tid = threadIdx.x, w = tid >> 5, lane = tid & 31;
    const int qt = 7 - blockIdx.x;            // heavy CTAs first
    const int n  = blockIdx.y >> 4, h = blockIdx.y & 15, b = blockIdx.z;
    const int sc = b * 16 + h;
    const int qbase = qt * 128;
    const int la = lane >> 2, lb = lane & 3;
    const int nkt = 2 * qt + 2;

    // gmem fragment tile bases (u64 units)
    const uint64_t* pKH = g_KfH + ((uint32_t)sc * 1024 + n * 128) * 128;
    const uint64_t* pKL = g_KfL + ((uint32_t)sc * 1024 + n * 128) * 128;
    const uint64_t* pVH = g_VfH + ((uint32_t)sc * 128 + n * 16) * 1024;
    const uint64_t* pVL = g_VfL + ((uint32_t)sc * 128 + n * 16) * 1024;

    // kick off copy of tile 0
    {
        uint32_t dst = sb + tid * 16;
        const uint32_t o2 = (uint32_t)tid * 2;
        #pragma unroll
        for (int i = 0; i < 4; i++) {
            cpa16(dst + P_KH + i * 2048, pKH + o2 + i * 256);
            cpa16(dst + P_KL + i * 2048, pKL + o2 + i * 256);
            cpa16(dst + P_VH + i * 2048, pVH + o2 + i * 256);
            cpa16(dst + P_VL + i * 2048, pVL + o2 + i * 256);
        }
        CP_COMMIT();
    }

    // ---------- Q: load + RoPE(+log2e) + bf16 split -> A fragments (M=32) ----------
    uint32_t Qhi[4][2][4], Qlo[4][2][4];
    {
        const int bq = lb * 2;
        float rot[4][4][4];                     // [rgroup][t][i]
        #pragma unroll
        for (int r = 0; r < 4; r++) {
            int m  = 32 * w + la + 8 * r;       // rgroup r: mt=r>>1, rr=r&1
            int lq = n * C_ + qbase + m;
            const float* gq = q + (((long)b * L_ + lq) * H_ + h) * D_;
            const float* gc = g_cos + lq * 32;
            const float* gs = g_sin + lq * 32;
            float xv[4][4], cs[2][4], sn[2][4];
            #pragma unroll
            for (int t = 0; t < 4; t++) {
                float2 u0 = *(const float2*)(gq + 16 * t + bq);
                float2 u1 = *(const float2*)(gq + 16 * t + bq + 8);
                xv[t][0] = u0.x; xv[t][1] = u0.y; xv[t][2] = u1.x; xv[t][3] = u1.y;
            }
            #pragma unroll
            for (int t = 0; t < 2; t++) {
                float2 c0 = *(const float2*)(gc + 16 * t + bq);
                float2 c1 = *(const float2*)(gc + 16 * t + bq + 8);
                cs[t][0] = c0.x; cs[t][1] = c0.y; cs[t][2] = c1.x; cs[t][3] = c1.y;
                float2 s0 = *(const float2*)(gs + 16 * t + bq);
                float2 s1 = *(const float2*)(gs + 16 * t + bq + 8);
                sn[t][0] = s0.x; sn[t][1] = s0.y; sn[t][2] = s1.x; sn[t][3] = s1.y;
            }
            #pragma unroll
            for (int t = 0; t < 2; t++)
                #pragma unroll
                for (int i = 0; i < 4; i++) {
                    rot[r][t][i]   = (xv[t][i] * cs[t][i] - xv[t+2][i] * sn[t][i]) * LOG2E;
                    rot[r][t+2][i] = (xv[t+2][i] * cs[t][i] + xv[t][i] * sn[t][i]) * LOG2E;
                }
        }
        #pragma unroll
        for (int mt = 0; mt < 2; mt++)
            #pragma unroll
            for (int t = 0; t < 4; t++) {
                pack_hilo(rot[2*mt  ][t][0], rot[2*mt  ][t][1], Qhi[t][mt][0], Qlo[t][mt][0]);
                pack_hilo(rot[2*mt+1][t][0], rot[2*mt+1][t][1], Qhi[t][mt][1], Qlo[t][mt][1]);
                pack_hilo(rot[2*mt  ][t][2], rot[2*mt  ][t][3], Qhi[t][mt][2], Qlo[t][mt][2]);
                pack_hilo(rot[2*mt+1][t][2], rot[2*mt+1][t][3], Qhi[t][mt][3], Qlo[t][mt][3]);
            }
    }

    float o[2][8][4];
    #pragma unroll
    for (int mt = 0; mt < 2; mt++)
        #pragma unroll
        for (int j = 0; j < 8; j++)
            #pragma unroll
            for (int i = 0; i < 4; i++) o[mt][j][i] = 0.f;
    float ls[2][2] = {{0.f, 0.f}, {0.f, 0.f}};

    const int rowA0 = qbase + 32 * w + la;       // mt=0
    const int rowA1 = rowA0 + 8;
    const int rowB0 = rowA0 + 16;                // mt=1
    const int rowB1 = rowA0 + 24;

    for (int kt = 0; kt < nkt; kt++) {
        const int kbase = kt * BK;
        CP_WAIT0();
        __syncthreads();
        if (kt + 1 < nkt) {                       // prefetch next tile
            uint32_t dst = sb + ((kt + 1) & 1) * BUFB + tid * 16;
            const uint32_t o2 = (uint32_t)(kt + 1) * 1024 + (uint32_t)tid * 2;
            #pragma unroll
            for (int i = 0; i < 4; i++) {
                cpa16(dst + P_KH + i * 2048, pKH + o2 + i * 256);
                cpa16(dst + P_KL + i * 2048, pKL + o2 + i * 256);
                cpa16(dst + P_VH + i * 2048, pVH + o2 + i * 256);
                cpa16(dst + P_VL + i * 2048, pVL + o2 + i * 256);
            }
            CP_COMMIT();
        }
        const uint32_t KB = sb + (kt & 1) * BUFB;
        const uint32_t fo = (uint32_t)(la * 32 + lb * 8);

        // ---------- S = Q @ K^T (3-pass split, both m-tiles share B frags) ----------
        float c[2][8][4];
        #pragma unroll
        for (int mt = 0; mt < 2; mt++)
            #pragma unroll
            for (int j = 0; j < 8; j++)
                #pragma unroll
                for (int i = 0; i < 4; i++) c[mt][j][i] = 0.f;

        #pragma unroll
        for (int t = 0; t < 4; t++) {
            #pragma unroll
            for (int j = 0; j < 8; j++) {
                uint32_t a = KB + P_KH + (uint32_t)j * 1024 + (uint32_t)t * 256 + fo;
                uint32_t bh0, bh1, bl0, bl1;
                lds64(bh0, bh1, a);
                lds64(bl0, bl1, a + (P_KL - P_KH));
                mma_bf16(c[0][j], Qhi[t][0], bh0, bh1);
                mma_bf16(c[1][j], Qhi[t][1], bh0, bh1);
                mma_bf16(c[0][j], Qlo[t][0], bh0, bh1);
                mma_bf16(c[1][j], Qlo[t][1], bh0, bh1);
                mma_bf16(c[0][j], Qhi[t][0], bl0, bl1);
                mma_bf16(c[1][j], Qhi[t][1], bl0, bl1);
            }
        }

        // ---------- mask + exp2 + repack P (registers only) ----------
        uint32_t Phi[2][4][4], Plo[2][4][4];
        #pragma unroll
        for (int j = 0; j < 8; j++) {
            int col = kbase + 8 * j + lb * 2;
            float pA0 = (col     > rowA0) ? 0.f : ex2f(c[0][j][0]);
            float pA1 = (col + 1 > rowA0) ? 0.f : ex2f(c[0][j][1]);
            float pA2 = (col     > rowA1) ? 0.f : ex2f(c[0][j][2]);
            float pA3 = (col + 1 > rowA1) ? 0.f : ex2f(c[0][j][3]);
            float pB0 = (col     > rowB0) ? 0.f : ex2f(c[1][j][0]);
            float pB1 = (col + 1 > rowB0) ? 0.f : ex2f(c[1][j][1]);
            float pB2 = (col     > rowB1) ? 0.f : ex2f(c[1][j][2]);
            float pB3 = (col + 1 > rowB1) ? 0.f : ex2f(c[1][j][3]);
            ls[0][0] += pA0 + pA1; ls[0][1] += pA2 + pA3;
            ls[1][0] += pB0 + pB1; ls[1][1] += pB2 + pB3;
            int t = j >> 1, off = (j & 1) ? 2 : 0;
            pack_hilo(pA0, pA1, Phi[0][t][off],     Plo[0][t][off]);
            pack_hilo(pA2, pA3, Phi[0][t][off + 1], Plo[0][t][off + 1]);
            pack_hilo(pB0, pB1, Phi[1][t][off],     Plo[1][t][off]);
            pack_hilo(pB2, pB3, Phi[1][t][off + 1], Plo[1][t][off + 1]);
        }

        // ---------- O += P @ V (3-pass split) ----------
        #pragma unroll
        for (int t = 0; t < 4; t++) {
            #pragma unroll
            for (int j = 0; j < 8; j++) {
                uint32_t a = KB + P_VH + (uint32_t)t * 2048 + (uint32_t)j * 256 + fo;
                uint32_t bh0, bh1, bl0, bl1;
                lds64(bh0, bh1, a);
                lds64(bl0, bl1, a + (P_VL - P_VH));
                mma_bf16(o[0][j], Phi[0][t], bh0, bh1);
                mma_bf16(o[1][j], Phi[1][t], bh0, bh1);
                mma_bf16(o[0][j], Plo[0][t], bh0, bh1);
                mma_bf16(o[1][j], Plo[1][t], bh0, bh1);
                mma_bf16(o[0][j], Phi[0][t], bl0, bl1);
                mma_bf16(o[1][j], Phi[1][t], bl0, bl1);
            }
        }
    }

    // ---------- normalize + store ----------
    #pragma unroll
    for (int mt = 0; mt < 2; mt++)
        #pragma unroll
        for (int i = 0; i < 2; i++) {
            ls[mt][i] += __shfl_xor_sync(0xffffffffu, ls[mt][i], 1);
            ls[mt][i] += __shfl_xor_sync(0xffffffffu, ls[mt][i], 2);
        }
    #pragma unroll
    for (int mt = 0; mt < 2; mt++) {
        float inv0 = 1.0f / ls[mt][0], inv1 = 1.0f / ls[mt][1];
        int r0 = qbase + 32 * w + 16 * mt + la;
        const int lq0 = n * C_ + r0, lq1 = lq0 + 8;
        float* g0 = out + (((long)b * L_ + lq0) * H_ + h) * D_;
        float* g1 = out + (((long)b * L_ + lq1) * H_ + h) * D_;
        #pragma unroll
        for (int j = 0; j < 8; j++) {
            int d = 8 * j + lb * 2;
            *(float2*)(g0 + d) = make_float2(o[mt][j][0] * inv0, o[mt][j][1] * inv0);
            *(float2*)(g1 + d) = make_float2(o[mt][j][2] * inv1, o[mt][j][3] * inv1);
        }
    }
}

extern "C" void kernel_launch(void* const* d_in, const int* in_sizes, int n_in,
                              void* d_out, int out_size) {
    const float* q = (const float*)d_in[0];
    const float* k = (const float*)d_in[1];
    const float* v = (const float*)d_in[2];
    const int* st  = (const int*)d_in[3];
    float* out     = (float*)d_out;

    cudaFuncSetAttribute(attn_k, cudaFuncAttributeMaxDynamicSharedMemorySize, 2 * BUFB);

    rope_table_k<<<(L_ * 32 + 255) / 256, 256>>>(st);
    prep_k<<<8192, 256>>>(k);
    prep_v<<<16384, 256>>>(v);
    attn_k<<<dim3(8, (L_ / C_) * H_, B_), 128, 2 * BUFB>>>(q, out);
}

// round 10
// speedup vs baseline: 2.2443x; 1.2036x over previous
#include <cuda_runtime.h>
#include <cuda_fp16.h>
#include <math.h>
#include <stdint.h>

#define B_  2
#define L_  8192
#define H_  16
#define D_  64
#define C_  1024
#define BK  64
#define LOG2E 1.4426950408889634f

__device__ float g_cos[L_ * 32];
__device__ float g_sin[L_ * 32];

// fragment-ready scratch (u64 units): K hi/lo fp16, V single fp16
__device__ uint64_t g_KfH[4194304];
__device__ uint64_t g_KfL[4194304];
__device__ uint64_t g_Vf [4194304];

__global__ void rope_table_k(const int* __restrict__ startp) {
    int i = blockIdx.x * blockDim.x + threadIdx.x;
    if (i >= L_ * 32) return;
    int pos = *startp + (i >> 5);
    int j = i & 31;
    float invf = (float)(1.0 / pow(10000.0, (double)j / 32.0));
    float ang  = (float)pos * invf;
    g_cos[i] = (float)cos((double)ang);
    g_sin[i] = (float)sin((double)ang);
}

// ---------------- helpers ----------------
__device__ __forceinline__ uint32_t smem_u32(const void* p) {
    uint32_t a;
    asm("{ .reg .u64 t; cvta.to.shared.u64 t, %1; cvt.u32.u64 %0, t; }" : "=r"(a) : "l"(p));
    return a;
}
__device__ __forceinline__ float ex2f(float x) {
    float y; asm("ex2.approx.ftz.f32 %0, %1;" : "=f"(y) : "f"(x)); return y;
}
__device__ __forceinline__ void lds64(uint32_t& x, uint32_t& y, uint32_t a) {
    asm volatile("ld.shared.v2.b32 {%0,%1}, [%2];" : "=r"(x), "=r"(y) : "r"(a));
}
__device__ __forceinline__ void cpa16(uint32_t s, const uint64_t* g) {
    asm volatile("cp.async.cg.shared.global [%0], [%1], 16;" :: "r"(s), "l"(g));
}
#define CP_COMMIT() asm volatile("cp.async.commit_group;" ::: "memory")
#define CP_WAIT0()  asm volatile("cp.async.wait_group 0;" ::: "memory")
__device__ __forceinline__ void mma_f16(float* c, const uint32_t* a, uint32_t b0, uint32_t b1) {
    asm volatile(
        "mma.sync.aligned.m16n8k16.row.col.f32.f16.f16.f32 "
        "{%0,%1,%2,%3}, {%4,%5,%6,%7}, {%8,%9}, {%0,%1,%2,%3};"
        : "+f"(c[0]), "+f"(c[1]), "+f"(c[2]), "+f"(c[3])
        : "r"(a[0]), "r"(a[1]), "r"(a[2]), "r"(a[3]), "r"(b0), "r"(b1));
}
__device__ __forceinline__ uint32_t pack_h(float x0, float x1) {
    __half2 h = __floats2half2_rn(x0, x1);
    return *reinterpret_cast<uint32_t*>(&h);
}
__device__ __forceinline__ void pack_hilo_h(float x0, float x1, uint32_t& hi, uint32_t& lo) {
    __half2 h = __floats2half2_rn(x0, x1);
    float2 hf = __half22float2(h);
    __half2 l = __floats2half2_rn(x0 - hf.x, x1 - hf.y);
    hi = *reinterpret_cast<uint32_t*>(&h);
    lo = *reinterpret_cast<uint32_t*>(&l);
}

// ---------------- prep: K -> RoPE'd fp16 hi/lo fragments ----------------
__global__ void prep_k(const float* __restrict__ k) {
    uint32_t g = blockIdx.x * blockDim.x + threadIdx.x;
    int lb = g & 3, la = (g >> 2) & 7, t01 = (g >> 5) & 1, m = (g >> 6) & 1023;
    int sc = g >> 16;
    int b = sc >> 4, h = sc & 15;
    int l = 8 * m + la;
    const float* gk = k + (((long)b * L_ + l) * H_ + h) * D_;
    int d0 = 16 * t01 + 2 * lb;
    float2 x0 = *(const float2*)(gk + d0);
    float2 x1 = *(const float2*)(gk + d0 + 8);
    float2 y0 = *(const float2*)(gk + d0 + 32);
    float2 y1 = *(const float2*)(gk + d0 + 40);
    float2 c0 = *(const float2*)(g_cos + l * 32 + d0);
    float2 c1 = *(const float2*)(g_cos + l * 32 + d0 + 8);
    float2 s0 = *(const float2*)(g_sin + l * 32 + d0);
    float2 s1 = *(const float2*)(g_sin + l * 32 + d0 + 8);
    uint32_t hA, lA, hB, lB;
    pack_hilo_h(x0.x*c0.x - y0.x*s0.x, x0.y*c0.y - y0.y*s0.y, hA, lA);
    pack_hilo_h(x1.x*c1.x - y1.x*s1.x, x1.y*c1.y - y1.y*s1.y, hB, lB);
    uint64_t loHi = (uint64_t)hA | ((uint64_t)hB << 32);
    uint64_t loLo = (uint64_t)lA | ((uint64_t)lB << 32);
    pack_hilo_h(y0.x*c0.x + x0.x*s0.x, y0.y*c0.y + x0.y*s0.y, hA, lA);
    pack_hilo_h(y1.x*c1.x + x1.x*s1.x, y1.y*c1.y + x1.y*s1.y, hB, lB);
    uint64_t hiHi = (uint64_t)hA | ((uint64_t)hB << 32);
    uint64_t hiLo = (uint64_t)lA | ((uint64_t)lB << 32);
    uint32_t base = ((uint32_t)sc * 1024 + m) * 128 + la * 4 + lb;
    g_KfH[base + t01 * 32]       = loHi;
    g_KfL[base + t01 * 32]       = loLo;
    g_KfH[base + (t01 + 2) * 32] = hiHi;
    g_KfL[base + (t01 + 2) * 32] = hiLo;
}

// ---------------- prep: V -> transposed single-fp16 fragments (smem transpose) ----------
__global__ void __launch_bounds__(256, 4) prep_v(const float* __restrict__ v) {
    __shared__ float tile[64][65];
    const int blk = blockIdx.x;              // sc*128 + gt
    const int sc = blk >> 7, gt = blk & 127;
    const int b = sc >> 4, h = sc & 15;
    const int t = threadIdx.x;
    {
        const int r = t >> 2, dseg = (t & 3) * 16;
        const float* gv = v + (((long)b * L_ + (gt * 64 + r)) * H_ + h) * D_ + dseg;
        float a0[4], a1[4], a2[4], a3[4];
        *(float4*)a0 = *(const float4*)(gv);
        *(float4*)a1 = *(const float4*)(gv + 4);
        *(float4*)a2 = *(const float4*)(gv + 8);
        *(float4*)a3 = *(const float4*)(gv + 12);
        #pragma unroll
        for (int i = 0; i < 4; i++) {
            tile[r][dseg + i]      = a0[i];
            tile[r][dseg + 4 + i]  = a1[i];
            tile[r][dseg + 8 + i]  = a2[i];
            tile[r][dseg + 12 + i] = a3[i];
        }
    }
    __syncthreads();
    const int lb = t & 3, d = (t >> 2) & 63;
    uint64_t* outp = g_Vf + ((uint32_t)(sc * 128 + gt)) * 1024 + d * 4 + lb;
    #pragma unroll
    for (int t2 = 0; t2 < 4; t2++) {
        int r0 = t2 * 16 + 2 * lb;
        uint32_t w0 = pack_h(tile[r0][d],     tile[r0 + 1][d]);
        uint32_t w1 = pack_h(tile[r0 + 8][d], tile[r0 + 9][d]);
        outp[t2 * 256] = (uint64_t)w0 | ((uint64_t)w1 << 32);
    }
}

// smem per buffer: KH 8KB | KL 8KB | V 8KB = 24KB; double buffered = 48KB
#define BUFB 24576
#define P_KH 0
#define P_KL 8192
#define P_V  16384

// ---------------- main: 4 warps, M=32/warp, fp16 5-pass, running max ----------------
__global__ void __launch_bounds__(128, 2)
attn_k(const float* __restrict__ q, float* __restrict__ out) {
    extern __shared__ __align__(16) char smc[];
    const uint32_t sb = smem_u32(smc);
    const int tid = threadIdx.x, w = tid >> 5, lane = tid & 31;
    const int qt = 7 - blockIdx.x;            // heavy CTAs first
    const int n  = blockIdx.y >> 4, h = blockIdx.y & 15, b = blockIdx.z;
    const int sc = b * 16 + h;
    const int qbase = qt * 128;
    const int la = lane >> 2, lb = lane & 3;
    const int nkt = 2 * qt + 2;

    const uint64_t* pKH = g_KfH + ((uint32_t)sc * 1024 + n * 128) * 128;
    const uint64_t* pKL = g_KfL + ((uint32_t)sc * 1024 + n * 128) * 128;
    const uint64_t* pV  = g_Vf  + ((uint32_t)sc * 128  + n * 16 ) * 1024;

    // kick off copy of tile 0
    {
        uint32_t dst = sb + tid * 16;
        const uint32_t o2 = (uint32_t)tid * 2;
        #pragma unroll
        for (int i = 0; i < 4; i++) {
            cpa16(dst + P_KH + i * 2048, pKH + o2 + i * 256);
            cpa16(dst + P_KL + i * 2048, pKL + o2 + i * 256);
            cpa16(dst + P_V  + i * 2048, pV  + o2 + i * 256);
        }
        CP_COMMIT();
    }

    // ---------- Q: load + RoPE(+log2e) + fp16 split -> A fragments (M=32) ----------
    uint32_t Qhi[4][2][4], Qlo[4][2][4];
    {
        const int bq = lb * 2;
        float rot[4][4][4];
        #pragma unroll
        for (int r = 0; r < 4; r++) {
            int m  = 32 * w + la + 8 * r;
            int lq = n * C_ + qbase + m;
            const float* gq = q + (((long)b * L_ + lq) * H_ + h) * D_;
            const float* gc = g_cos + lq * 32;
            const float* gs = g_sin + lq * 32;
            float xv[4][4], cs[2][4], sn[2][4];
            #pragma unroll
            for (int t = 0; t < 4; t++) {
                float2 u0 = *(const float2*)(gq + 16 * t + bq);
                float2 u1 = *(const float2*)(gq + 16 * t + bq + 8);
                xv[t][0] = u0.x; xv[t][1] = u0.y; xv[t][2] = u1.x; xv[t][3] = u1.y;
            }
            #pragma unroll
            for (int t = 0; t < 2; t++) {
                float2 c0 = *(const float2*)(gc + 16 * t + bq);
                float2 c1 = *(const float2*)(gc + 16 * t + bq + 8);
                cs[t][0] = c0.x; cs[t][1] = c0.y; cs[t][2] = c1.x; cs[t][3] = c1.y;
                float2 s0 = *(const float2*)(gs + 16 * t + bq);
                float2 s1 = *(const float2*)(gs + 16 * t + bq + 8);
                sn[t][0] = s0.x; sn[t][1] = s0.y; sn[t][2] = s1.x; sn[t][3] = s1.y;
            }
            #pragma unroll
            for (int t = 0; t < 2; t++)
                #pragma unroll
                for (int i = 0; i < 4; i++) {
                    rot[r][t][i]   = (xv[t][i] * cs[t][i] - xv[t+2][i] * sn[t][i]) * LOG2E;
                    rot[r][t+2][i] = (xv[t+2][i] * cs[t][i] + xv[t][i] * sn[t][i]) * LOG2E;
                }
        }
        #pragma unroll
        for (int mt = 0; mt < 2; mt++)
            #pragma unroll
            for (int t = 0; t < 4; t++) {
                pack_hilo_h(rot[2*mt  ][t][0], rot[2*mt  ][t][1], Qhi[t][mt][0], Qlo[t][mt][0]);
                pack_hilo_h(rot[2*mt+1][t][0], rot[2*mt+1][t][1], Qhi[t][mt][1], Qlo[t][mt][1]);
                pack_hilo_h(rot[2*mt  ][t][2], rot[2*mt  ][t][3], Qhi[t][mt][2], Qlo[t][mt][2]);
                pack_hilo_h(rot[2*mt+1][t][2], rot[2*mt+1][t][3], Qhi[t][mt][3], Qlo[t][mt][3]);
            }
    }

    float o[2][8][4];
    #pragma unroll
    for (int mt = 0; mt < 2; mt++)
        #pragma unroll
        for (int j = 0; j < 8; j++)
            #pragma unroll
            for (int i = 0; i < 4; i++) o[mt][j][i] = 0.f;
    float ls[2][2] = {{0.f, 0.f}, {0.f, 0.f}};
    float m_[2][2] = {{-1e30f, -1e30f}, {-1e30f, -1e30f}};

    const int rowA0 = qbase + 32 * w + la;
    const int rowA1 = rowA0 + 8;
    const int rowB0 = rowA0 + 16;
    const int rowB1 = rowA0 + 24;

    for (int kt = 0; kt < nkt; kt++) {
        const int kbase = kt * BK;
        CP_WAIT0();
        __syncthreads();
        if (kt + 1 < nkt) {
            uint32_t dst = sb + ((kt + 1) & 1) * BUFB + tid * 16;
            const uint32_t o2 = (uint32_t)(kt + 1) * 1024 + (uint32_t)tid * 2;
            #pragma unroll
            for (int i = 0; i < 4; i++) {
                cpa16(dst + P_KH + i * 2048, pKH + o2 + i * 256);
                cpa16(dst + P_KL + i * 2048, pKL + o2 + i * 256);
                cpa16(dst + P_V  + i * 2048, pV  + o2 + i * 256);
            }
            CP_COMMIT();
        }
        const uint32_t KB = sb + (kt & 1) * BUFB;
        const uint32_t fo = (uint32_t)(la * 32 + lb * 8);

        // ---------- S = Q @ K^T (3-pass fp16 split) ----------
        float c[2][8][4];
        #pragma unroll
        for (int mt = 0; mt < 2; mt++)
            #pragma unroll
            for (int j = 0; j < 8; j++)
                #pragma unroll
                for (int i = 0; i < 4; i++) c[mt][j][i] = 0.f;

        #pragma unroll
        for (int t = 0; t < 4; t++) {
            #pragma unroll
            for (int j = 0; j < 8; j++) {
                uint32_t a = KB + P_KH + (uint32_t)j * 1024 + (uint32_t)t * 256 + fo;
                uint32_t bh0, bh1, bl0, bl1;
                lds64(bh0, bh1, a);
                lds64(bl0, bl1, a + (P_KL - P_KH));
                mma_f16(c[0][j], Qhi[t][0], bh0, bh1);
                mma_f16(c[1][j], Qhi[t][1], bh0, bh1);
                mma_f16(c[0][j], Qlo[t][0], bh0, bh1);
                mma_f16(c[1][j], Qlo[t][1], bh0, bh1);
                mma_f16(c[0][j], Qhi[t][0], bl0, bl1);
                mma_f16(c[1][j], Qhi[t][1], bl0, bl1);
            }
        }

        // ---------- mask ----------
        if (kbase + BK > rowA0) {
            #pragma unroll
            for (int j = 0; j < 8; j++) {
                int col = kbase + 8 * j + lb * 2;
                if (col     > rowA0) c[0][j][0] = -1e30f;
                if (col + 1 > rowA0) c[0][j][1] = -1e30f;
                if (col     > rowA1) c[0][j][2] = -1e30f;
                if (col + 1 > rowA1) c[0][j][3] = -1e30f;
                if (col     > rowB0) c[1][j][0] = -1e30f;
                if (col + 1 > rowB0) c[1][j][1] = -1e30f;
                if (col     > rowB1) c[1][j][2] = -1e30f;
                if (col + 1 > rowB1) c[1][j][3] = -1e30f;
            }
        }

        // ---------- running max update + O/ls rescale ----------
        float scl[2][2];
        #pragma unroll
        for (int mt = 0; mt < 2; mt++)
            #pragma unroll
            for (int rh = 0; rh < 2; rh++) {
                float mx = -1e30f;
                #pragma unroll
                for (int j = 0; j < 8; j++)
                    mx = fmaxf(mx, fmaxf(c[mt][j][2*rh], c[mt][j][2*rh+1]));
                mx = fmaxf(mx, __shfl_xor_sync(0xffffffffu, mx, 1));
                mx = fmaxf(mx, __shfl_xor_sync(0xffffffffu, mx, 2));
                float mn = fmaxf(m_[mt][rh], mx);
                float s = ex2f(m_[mt][rh] - mn);
                m_[mt][rh] = mn;
                scl[mt][rh] = s;
                ls[mt][rh] *= s;
            }
        #pragma unroll
        for (int mt = 0; mt < 2; mt++)
            #pragma unroll
            for (int j = 0; j < 8; j++) {
                o[mt][j][0] *= scl[mt][0]; o[mt][j][1] *= scl[mt][0];
                o[mt][j][2] *= scl[mt][1]; o[mt][j][3] *= scl[mt][1];
            }

        // ---------- exp2 + repack P (fp16 hi/lo, in [0,1]) ----------
        uint32_t Phi[2][4][4], Plo[2][4][4];
        #pragma unroll
        for (int j = 0; j < 8; j++) {
            float pA0 = ex2f(c[0][j][0] - m_[0][0]);
            float pA1 = ex2f(c[0][j][1] - m_[0][0]);
            float pA2 = ex2f(c[0][j][2] - m_[0][1]);
            float pA3 = ex2f(c[0][j][3] - m_[0][1]);
            float pB0 = ex2f(c[1][j][0] - m_[1][0]);
            float pB1 = ex2f(c[1][j][1] - m_[1][0]);
            float pB2 = ex2f(c[1][j][2] - m_[1][1]);
            float pB3 = ex2f(c[1][j][3] - m_[1][1]);
            ls[0][0] += pA0 + pA1; ls[0][1] += pA2 + pA3;
            ls[1][0] += pB0 + pB1; ls[1][1] += pB2 + pB3;
            int t = j >> 1, off = (j & 1) ? 2 : 0;
            pack_hilo_h(pA0, pA1, Phi[0][t][off],     Plo[0][t][off]);
            pack_hilo_h(pA2, pA3, Phi[0][t][off + 1], Plo[0][t][off + 1]);
            pack_hilo_h(pB0, pB1, Phi[1][t][off],     Plo[1][t][off]);
            pack_hilo_h(pB2, pB3, Phi[1][t][off + 1], Plo[1][t][off + 1]);
        }

        // ---------- O += P @ V (2-pass: Phi·V + Plo·V, single-fp16 V) ----------
        #pragma unroll
        for (int t = 0; t < 4; t++) {
            #pragma unroll
            for (int j = 0; j < 8; j++) {
                uint32_t a = KB + P_V + (uint32_t)t * 2048 + (uint32_t)j * 256 + fo;
                uint32_t bv0, bv1;
                lds64(bv0, bv1, a);
                mma_f16(o[0][j], Phi[0][t], bv0, bv1);
                mma_f16(o[1][j], Phi[1][t], bv0, bv1);
                mma_f16(o[0][j], Plo[0][t], bv0, bv1);
                mma_f16(o[1][j], Plo[1][t], bv0, bv1);
            }
        }
    }

    // ---------- normalize + store ----------
    #pragma unroll
    for (int mt = 0; mt < 2; mt++)
        #pragma unroll
        for (int i = 0; i < 2; i++) {
            ls[mt][i] += __shfl_xor_sync(0xffffffffu, ls[mt][i], 1);
            ls[mt][i] += __shfl_xor_sync(0xffffffffu, ls[mt][i], 2);
        }
    #pragma unroll
    for (int mt = 0; mt < 2; mt++) {
        float inv0 = 1.0f / ls[mt][0], inv1 = 1.0f / ls[mt][1];
        int r0 = qbase + 32 * w + 16 * mt + la;
        const int lq0 = n * C_ + r0, lq1 = lq0 + 8;
        float* g0 = out + (((long)b * L_ + lq0) * H_ + h) * D_;
        float* g1 = out + (((long)b * L_ + lq1) * H_ + h) * D_;
        #pragma unroll
        for (int j = 0; j < 8; j++) {
            int d = 8 * j + lb * 2;
            *(float2*)(g0 + d) = make_float2(o[mt][j][0] * inv0, o[mt][j][1] * inv0);
            *(float2*)(g1 + d) = make_float2(o[mt][j][2] * inv1, o[mt][j][3] * inv1);
        }
    }
}

extern "C" void kernel_launch(void* const* d_in, const int* in_sizes, int n_in,
                              void* d_out, int out_size) {
    const float* q = (const float*)d_in[0];
    const float* k = (const float*)d_in[1];
    const float* v = (const float*)d_in[2];
    const int* st  = (const int*)d_in[3];
    float* out     = (float*)d_out;

    cudaFuncSetAttribute(attn_k, cudaFuncAttributeMaxDynamicSharedMemorySize, 2 * BUFB);

    rope_table_k<<<(L_ * 32 + 255) / 256, 256>>>(st);
    prep_k<<<8192, 256>>>(k);
    prep_v<<<4096, 256>>>(v);
    attn_k<<<dim3(8, (L_ / C_) * H_, B_), 128, 2 * BUFB>>>(q, out);
}

// round 11
// speedup vs baseline: 2.6424x; 1.1774x over previous
#include <cuda_runtime.h>
#include <cuda_fp16.h>
#include <math.h>
#include <stdint.h>

#define B_  2
#define L_  8192
#define H_  16
#define D_  64
#define C_  1024
#define BK  64
#define LOG2E 1.4426950408889634f

__device__ float g_cos[L_ * 32];
__device__ float g_sin[L_ * 32];

// fragment-ready scratch (u64 units): K hi/lo fp16, V single fp16
__device__ uint64_t g_KfH[4194304];
__device__ uint64_t g_KfL[4194304];
__device__ uint64_t g_Vf [4194304];

__global__ void rope_table_k(const int* __restrict__ startp) {
    int i = blockIdx.x * blockDim.x + threadIdx.x;
    if (i >= L_ * 32) return;
    int pos = *startp + (i >> 5);
    int j = i & 31;
    float invf = (float)(1.0 / pow(10000.0, (double)j / 32.0));
    float ang  = (float)pos * invf;
    g_cos[i] = (float)cos((double)ang);
    g_sin[i] = (float)sin((double)ang);
}

// ---------------- helpers ----------------
__device__ __forceinline__ uint32_t smem_u32(const void* p) {
    uint32_t a;
    asm("{ .reg .u64 t; cvta.to.shared.u64 t, %1; cvt.u32.u64 %0, t; }" : "=r"(a) : "l"(p));
    return a;
}
__device__ __forceinline__ float ex2f(float x) {
    float y; asm("ex2.approx.ftz.f32 %0, %1;" : "=f"(y) : "f"(x)); return y;
}
__device__ __forceinline__ void lds64(uint32_t& x, uint32_t& y, uint32_t a) {
    asm volatile("ld.shared.v2.b32 {%0,%1}, [%2];" : "=r"(x), "=r"(y) : "r"(a));
}
__device__ __forceinline__ void cpa16(uint32_t s, const uint64_t* g) {
    asm volatile("cp.async.cg.shared.global [%0], [%1], 16;" :: "r"(s), "l"(g));
}
#define CP_COMMIT() asm volatile("cp.async.commit_group;" ::: "memory")
#define CP_WAIT0()  asm volatile("cp.async.wait_group 0;" ::: "memory")
__device__ __forceinline__ void mma_f16(float* c, const uint32_t* a, uint32_t b0, uint32_t b1) {
    asm volatile(
        "mma.sync.aligned.m16n8k16.row.col.f32.f16.f16.f32 "
        "{%0,%1,%2,%3}, {%4,%5,%6,%7}, {%8,%9}, {%0,%1,%2,%3};"
        : "+f"(c[0]), "+f"(c[1]), "+f"(c[2]), "+f"(c[3])
        : "r"(a[0]), "r"(a[1]), "r"(a[2]), "r"(a[3]), "r"(b0), "r"(b1));
}
__device__ __forceinline__ uint32_t pack_h(float x0, float x1) {
    __half2 h = __floats2half2_rn(x0, x1);
    return *reinterpret_cast<uint32_t*>(&h);
}
__device__ __forceinline__ void pack_hilo_h(float x0, float x1, uint32_t& hi, uint32_t& lo) {
    __half2 h = __floats2half2_rn(x0, x1);
    float2 hf = __half22float2(h);
    __half2 l = __floats2half2_rn(x0 - hf.x, x1 - hf.y);
    hi = *reinterpret_cast<uint32_t*>(&h);
    lo = *reinterpret_cast<uint32_t*>(&l);
}

// ---------------- fused prep: K -> RoPE'd fp16 hi/lo frags; V -> transposed fp16 frags --
__global__ void __launch_bounds__(256) prep_kv(const float* __restrict__ k,
                                               const float* __restrict__ v) {
    __shared__ float tile[64][65];
    if (blockIdx.x < 8192) {
        // ----- K part -----
        uint32_t g = blockIdx.x * 256 + threadIdx.x;
        int lb = g & 3, la = (g >> 2) & 7, t01 = (g >> 5) & 1, m = (g >> 6) & 1023;
        int sc = g >> 16;
        int b = sc >> 4, h = sc & 15;
        int l = 8 * m + la;
        const float* gk = k + (((long)b * L_ + l) * H_ + h) * D_;
        int d0 = 16 * t01 + 2 * lb;
        float2 x0 = *(const float2*)(gk + d0);
        float2 x1 = *(const float2*)(gk + d0 + 8);
        float2 y0 = *(const float2*)(gk + d0 + 32);
        float2 y1 = *(const float2*)(gk + d0 + 40);
        float2 c0 = *(const float2*)(g_cos + l * 32 + d0);
        float2 c1 = *(const float2*)(g_cos + l * 32 + d0 + 8);
        float2 s0 = *(const float2*)(g_sin + l * 32 + d0);
        float2 s1 = *(const float2*)(g_sin + l * 32 + d0 + 8);
        uint32_t hA, lA, hB, lB;
        pack_hilo_h(x0.x*c0.x - y0.x*s0.x, x0.y*c0.y - y0.y*s0.y, hA, lA);
        pack_hilo_h(x1.x*c1.x - y1.x*s1.x, x1.y*c1.y - y1.y*s1.y, hB, lB);
        uint64_t loHi = (uint64_t)hA | ((uint64_t)hB << 32);
        uint64_t loLo = (uint64_t)lA | ((uint64_t)lB << 32);
        pack_hilo_h(y0.x*c0.x + x0.x*s0.x, y0.y*c0.y + x0.y*s0.y, hA, lA);
        pack_hilo_h(y1.x*c1.x + x1.x*s1.x, y1.y*c1.y + x1.y*s1.y, hB, lB);
        uint64_t hiHi = (uint64_t)hA | ((uint64_t)hB << 32);
        uint64_t hiLo = (uint64_t)lA | ((uint64_t)lB << 32);
        uint32_t base = ((uint32_t)sc * 1024 + m) * 128 + la * 4 + lb;
        g_KfH[base + t01 * 32]       = loHi;
        g_KfL[base + t01 * 32]       = loLo;
        g_KfH[base + (t01 + 2) * 32] = hiHi;
        g_KfL[base + (t01 + 2) * 32] = hiLo;
    } else {
        // ----- V part (smem transpose; scalar smem stores: 65-f rows not 16B aligned) ----
        const int blk = blockIdx.x - 8192;       // sc*128 + gt
        const int sc = blk >> 7, gt = blk & 127;
        const int b = sc >> 4, h = sc & 15;
        const int t = threadIdx.x;
        {
            const int r = t >> 2, dseg = (t & 3) * 16;
            const float* gv = v + (((long)b * L_ + (gt * 64 + r)) * H_ + h) * D_ + dseg;
            float a0[4], a1[4], a2[4], a3[4];
            *(float4*)a0 = *(const float4*)(gv);
            *(float4*)a1 = *(const float4*)(gv + 4);
            *(float4*)a2 = *(const float4*)(gv + 8);
            *(float4*)a3 = *(const float4*)(gv + 12);
            #pragma unroll
            for (int i = 0; i < 4; i++) {
                tile[r][dseg + i]      = a0[i];
                tile[r][dseg + 4 + i]  = a1[i];
                tile[r][dseg + 8 + i]  = a2[i];
                tile[r][dseg + 12 + i] = a3[i];
            }
        }
        __syncthreads();
        const int lb = t & 3, d = (t >> 2) & 63;
        uint64_t* outp = g_Vf + ((uint32_t)(sc * 128 + gt)) * 1024 + d * 4 + lb;
        #pragma unroll
        for (int t2 = 0; t2 < 4; t2++) {
            int r0 = t2 * 16 + 2 * lb;
            uint32_t w0 = pack_h(tile[r0][d],     tile[r0 + 1][d]);
            uint32_t w1 = pack_h(tile[r0 + 8][d], tile[r0 + 9][d]);
            outp[t2 * 256] = (uint64_t)w0 | ((uint64_t)w1 << 32);
        }
    }
}

// smem per buffer: KH 8KB | KL 8KB | V 8KB = 24KB; double buffered = 48KB
#define BUFB 24576
#define P_KH 0
#define P_KL 8192
#define P_V  16384

// ---------------- main: 4 warps, M=32/warp, fp16 4-pass, running max ----------------
__global__ void __launch_bounds__(128, 2)
attn_k(const float* __restrict__ q, float* __restrict__ out) {
    extern __shared__ __align__(16) char smc[];
    const uint32_t sb = smem_u32(smc);
    const int tid = threadIdx.x, w = tid >> 5, lane = tid & 31;
    const int qt = 7 - blockIdx.x;            // heavy CTAs first
    const int n  = blockIdx.y >> 4, h = blockIdx.y & 15, b = blockIdx.z;
    const int sc = b * 16 + h;
    const int qbase = qt * 128;
    const int la = lane >> 2, lb = lane & 3;
    const int nkt = 2 * qt + 2;

    const uint64_t* pKH = g_KfH + ((uint32_t)sc * 1024 + n * 128) * 128;
    const uint64_t* pKL = g_KfL + ((uint32_t)sc * 1024 + n * 128) * 128;
    const uint64_t* pV  = g_Vf  + ((uint32_t)sc * 128  + n * 16 ) * 1024;

    // kick off copy of tile 0
    {
        uint32_t dst = sb + tid * 16;
        const uint32_t o2 = (uint32_t)tid * 2;
        #pragma unroll
        for (int i = 0; i < 4; i++) {
            cpa16(dst + P_KH + i * 2048, pKH + o2 + i * 256);
            cpa16(dst + P_KL + i * 2048, pKL + o2 + i * 256);
            cpa16(dst + P_V  + i * 2048, pV  + o2 + i * 256);
        }
        CP_COMMIT();
    }

    // ---------- Q: load + RoPE(+log2e) + fp16 split -> A fragments (M=32) ----------
    uint32_t Qhi[4][2][4], Qlo[4][2][4];
    {
        const int bq = lb * 2;
        float rot[4][4][4];
        #pragma unroll
        for (int r = 0; r < 4; r++) {
            int m  = 32 * w + la + 8 * r;
            int lq = n * C_ + qbase + m;
            const float* gq = q + (((long)b * L_ + lq) * H_ + h) * D_;
            const float* gc = g_cos + lq * 32;
            const float* gs = g_sin + lq * 32;
            float xv[4][4], cs[2][4], sn[2][4];
            #pragma unroll
            for (int t = 0; t < 4; t++) {
                float2 u0 = *(const float2*)(gq + 16 * t + bq);
                float2 u1 = *(const float2*)(gq + 16 * t + bq + 8);
                xv[t][0] = u0.x; xv[t][1] = u0.y; xv[t][2] = u1.x; xv[t][3] = u1.y;
            }
            #pragma unroll
            for (int t = 0; t < 2; t++) {
                float2 c0 = *(const float2*)(gc + 16 * t + bq);
                float2 c1 = *(const float2*)(gc + 16 * t + bq + 8);
                cs[t][0] = c0.x; cs[t][1] = c0.y; cs[t][2] = c1.x; cs[t][3] = c1.y;
                float2 s0 = *(const float2*)(gs + 16 * t + bq);
                float2 s1 = *(const float2*)(gs + 16 * t + bq + 8);
                sn[t][0] = s0.x; sn[t][1] = s0.y; sn[t][2] = s1.x; sn[t][3] = s1.y;
            }
            #pragma unroll
            for (int t = 0; t < 2; t++)
                #pragma unroll
                for (int i = 0; i < 4; i++) {
                    rot[r][t][i]   = (xv[t][i] * cs[t][i] - xv[t+2][i] * sn[t][i]) * LOG2E;
                    rot[r][t+2][i] = (xv[t+2][i] * cs[t][i] + xv[t][i] * sn[t][i]) * LOG2E;
                }
        }
        #pragma unroll
        for (int mt = 0; mt < 2; mt++)
            #pragma unroll
            for (int t = 0; t < 4; t++) {
                pack_hilo_h(rot[2*mt  ][t][0], rot[2*mt  ][t][1], Qhi[t][mt][0], Qlo[t][mt][0]);
                pack_hilo_h(rot[2*mt+1][t][0], rot[2*mt+1][t][1], Qhi[t][mt][1], Qlo[t][mt][1]);
                pack_hilo_h(rot[2*mt  ][t][2], rot[2*mt  ][t][3], Qhi[t][mt][2], Qlo[t][mt][2]);
                pack_hilo_h(rot[2*mt+1][t][2], rot[2*mt+1][t][3], Qhi[t][mt][3], Qlo[t][mt][3]);
            }
    }

    float o[2][8][4];
    #pragma unroll
    for (int mt = 0; mt < 2; mt++)
        #pragma unroll
        for (int j = 0; j < 8; j++)
            #pragma unroll
            for (int i = 0; i < 4; i++) o[mt][j][i] = 0.f;
    float ls[2][2] = {{0.f, 0.f}, {0.f, 0.f}};
    float m_[2][2] = {{-1e30f, -1e30f}, {-1e30f, -1e30f}};

    const int rowA0 = qbase + 32 * w + la;
    const int rowA1 = rowA0 + 8;
    const int rowB0 = rowA0 + 16;
    const int rowB1 = rowA0 + 24;

    for (int kt = 0; kt < nkt; kt++) {
        const int kbase = kt * BK;
        CP_WAIT0();
        __syncthreads();
        if (kt + 1 < nkt) {
            uint32_t dst = sb + ((kt + 1) & 1) * BUFB + tid * 16;
            const uint32_t o2 = (uint32_t)(kt + 1) * 1024 + (uint32_t)tid * 2;
            #pragma unroll
            for (int i = 0; i < 4; i++) {
                cpa16(dst + P_KH + i * 2048, pKH + o2 + i * 256);
                cpa16(dst + P_KL + i * 2048, pKL + o2 + i * 256);
                cpa16(dst + P_V  + i * 2048, pV  + o2 + i * 256);
            }
            CP_COMMIT();
        }
        const uint32_t KB = sb + (kt & 1) * BUFB;
        const uint32_t fo = (uint32_t)(la * 32 + lb * 8);

        // ---------- S = Q @ K^T (3-pass fp16 split, j-pair interleaved) ----------
        float c[2][8][4];
        #pragma unroll
        for (int mt = 0; mt < 2; mt++)
            #pragma unroll
            for (int j = 0; j < 8; j++)
                #pragma unroll
                for (int i = 0; i < 4; i++) c[mt][j][i] = 0.f;

        #pragma unroll
        for (int t = 0; t < 4; t++) {
            #pragma unroll
            for (int j = 0; j < 8; j += 2) {
                uint32_t a0 = KB + P_KH + (uint32_t)j * 1024 + (uint32_t)t * 256 + fo;
                uint32_t bh0a, bh1a, bh0b, bh1b, bl0a, bl1a, bl0b, bl1b;
                lds64(bh0a, bh1a, a0);
                lds64(bh0b, bh1b, a0 + 1024);
                lds64(bl0a, bl1a, a0 + (P_KL - P_KH));
                lds64(bl0b, bl1b, a0 + (P_KL - P_KH) + 1024);
                mma_f16(c[0][j],   Qhi[t][0], bh0a, bh1a);
                mma_f16(c[0][j+1], Qhi[t][0], bh0b, bh1b);
                mma_f16(c[1][j],   Qhi[t][1], bh0a, bh1a);
                mma_f16(c[1][j+1], Qhi[t][1], bh0b, bh1b);
                mma_f16(c[0][j],   Qlo[t][0], bh0a, bh1a);
                mma_f16(c[0][j+1], Qlo[t][0], bh0b, bh1b);
                mma_f16(c[1][j],   Qlo[t][1], bh0a, bh1a);
                mma_f16(c[1][j+1], Qlo[t][1], bh0b, bh1b);
                mma_f16(c[0][j],   Qhi[t][0], bl0a, bl1a);
                mma_f16(c[0][j+1], Qhi[t][0], bl0b, bl1b);
                mma_f16(c[1][j],   Qhi[t][1], bl0a, bl1a);
                mma_f16(c[1][j+1], Qhi[t][1], bl0b, bl1b);
            }
        }

        // ---------- mask ----------
        if (kbase + BK > rowA0) {
            #pragma unroll
            for (int j = 0; j < 8; j++) {
                int col = kbase + 8 * j + lb * 2;
                if (col     > rowA0) c[0][j][0] = -1e30f;
                if (col + 1 > rowA0) c[0][j][1] = -1e30f;
                if (col     > rowA1) c[0][j][2] = -1e30f;
                if (col + 1 > rowA1) c[0][j][3] = -1e30f;
                if (col     > rowB0) c[1][j][0] = -1e30f;
                if (col + 1 > rowB0) c[1][j][1] = -1e30f;
                if (col     > rowB1) c[1][j][2] = -1e30f;
                if (col + 1 > rowB1) c[1][j][3] = -1e30f;
            }
        }

        // ---------- running max update + ls rescale ----------
        float scl[2][2];
        #pragma unroll
        for (int mt = 0; mt < 2; mt++)
            #pragma unroll
            for (int rh = 0; rh < 2; rh++) {
                float mx = -1e30f;
                #pragma unroll
                for (int j = 0; j < 8; j++)
                    mx = fmaxf(mx, fmaxf(c[mt][j][2*rh], c[mt][j][2*rh+1]));
                mx = fmaxf(mx, __shfl_xor_sync(0xffffffffu, mx, 1));
                mx = fmaxf(mx, __shfl_xor_sync(0xffffffffu, mx, 2));
                float mn = fmaxf(m_[mt][rh], mx);
                float s = ex2f(m_[mt][rh] - mn);
                m_[mt][rh] = mn;
                scl[mt][rh] = s;
                ls[mt][rh] *= s;
            }
        // O rescale only when some row's max moved (vote; late tiles mostly skip)
        bool need = (scl[0][0] != 1.f) | (scl[0][1] != 1.f) |
                    (scl[1][0] != 1.f) | (scl[1][1] != 1.f);
        if (__any_sync(0xffffffffu, need)) {
            #pragma unroll
            for (int mt = 0; mt < 2; mt++)
                #pragma unroll
                for (int j = 0; j < 8; j++) {
                    o[mt][j][0] *= scl[mt][0]; o[mt][j][1] *= scl[mt][0];
                    o[mt][j][2] *= scl[mt][1]; o[mt][j][3] *= scl[mt][1];
                }
        }

        // ---------- exp2 + pack P (single fp16 plane, in [0,1]) ----------
        uint32_t Phi[2][4][4];
        #pragma unroll
        for (int j = 0; j < 8; j++) {
            float pA0 = ex2f(c[0][j][0] - m_[0][0]);
            float pA1 = ex2f(c[0][j][1] - m_[0][0]);
            float pA2 = ex2f(c[0][j][2] - m_[0][1]);
            float pA3 = ex2f(c[0][j][3] - m_[0][1]);
            float pB0 = ex2f(c[1][j][0] - m_[1][0]);
            float pB1 = ex2f(c[1][j][1] - m_[1][0]);
            float pB2 = ex2f(c[1][j][2] - m_[1][1]);
            float pB3 = ex2f(c[1][j][3] - m_[1][1]);
            ls[0][0] += pA0 + pA1; ls[0][1] += pA2 + pA3;
            ls[1][0] += pB0 + pB1; ls[1][1] += pB2 + pB3;
            int t = j >> 1, off = (j & 1) ? 2 : 0;
            Phi[0][t][off]     = pack_h(pA0, pA1);
            Phi[0][t][off + 1] = pack_h(pA2, pA3);
            Phi[1][t][off]     = pack_h(pB0, pB1);
            Phi[1][t][off + 1] = pack_h(pB2, pB3);
        }

        // ---------- O += P @ V (single pass, j-pair interleaved) ----------
        #pragma unroll
        for (int t = 0; t < 4; t++) {
            #pragma unroll
            for (int j = 0; j < 8; j += 2) {
                uint32_t a0 = KB + P_V + (uint32_t)t * 2048 + (uint32_t)j * 256 + fo;
                uint32_t va0, va1, vb0, vb1;
                lds64(va0, va1, a0);
                lds64(vb0, vb1, a0 + 256);
                mma_f16(o[0][j],   Phi[0][t], va0, va1);
                mma_f16(o[0][j+1], Phi[0][t], vb0, vb1);
                mma_f16(o[1][j],   Phi[1][t], va0, va1);
                mma_f16(o[1][j+1], Phi[1][t], vb0, vb1);
            }
        }
    }

    // ---------- normalize + store ----------
    #pragma unroll
    for (int mt = 0; mt < 2; mt++)
        #pragma unroll
        for (int i = 0; i < 2; i++) {
            ls[mt][i] += __shfl_xor_sync(0xffffffffu, ls[mt][i], 1);
            ls[mt][i] += __shfl_xor_sync(0xffffffffu, ls[mt][i], 2);
        }
    #pragma unroll
    for (int mt = 0; mt < 2; mt++) {
        float inv0 = 1.0f / ls[mt][0], inv1 = 1.0f / ls[mt][1];
        int r0 = qbase + 32 * w + 16 * mt + la;
        const int lq0 = n * C_ + r0, lq1 = lq0 + 8;
        float* g0 = out + (((long)b * L_ + lq0) * H_ + h) * D_;
        float* g1 = out + (((long)b * L_ + lq1) * H_ + h) * D_;
        #pragma unroll
        for (int j = 0; j < 8; j++) {
            int d = 8 * j + lb * 2;
            *(float2*)(g0 + d) = make_float2(o[mt][j][0] * inv0, o[mt][j][1] * inv0);
            *(float2*)(g1 + d) = make_float2(o[mt][j][2] * inv1, o[mt][j][3] * inv1);
        }
    }
}

extern "C" void kernel_launch(void* const* d_in, const int* in_sizes, int n_in,
                              void* d_out, int out_size) {
    const float* q = (const float*)d_in[0];
    const float* k = (const float*)d_in[1];
    const float* v = (const float*)d_in[2];
    const int* st  = (const int*)d_in[3];
    float* out     = (float*)d_out;

    cudaFuncSetAttribute(attn_k, cudaFuncAttributeMaxDynamicSharedMemorySize, 2 * BUFB);

    rope_table_k<<<(L_ * 32 + 255) / 256, 256>>>(st);
    prep_kv<<<8192 + 4096, 256>>>(k, v);
    attn_k<<<dim3(8, (L_ / C_) * H_, B_), 128, 2 * BUFB>>>(q, out);
}

// round 12
// speedup vs baseline: 3.2139x; 1.2163x over previous
#include <cuda_runtime.h>
#include <cuda_fp16.h>
#include <math.h>
#include <stdint.h>

#define B_  2
#define L_  8192
#define H_  16
#define D_  64
#define C_  1024
#define BK  64
#define LOG2E 1.4426950408889634f

__device__ float g_invf[32];
__device__ float g_cos[L_ * 32];
__device__ float g_sin[L_ * 32];

// fragment-ready scratch (u64 units): K hi/lo fp16, V single fp16
__device__ uint64_t g_KfH[4194304];
__device__ uint64_t g_KfL[4194304];
__device__ uint64_t g_Vf [4194304];

// 32 threads: inv_freq = fp32(1/10000^(j/32)) via double pow (same chain as before)
__global__ void invf_k() {
    int j = threadIdx.x;
    if (j < 32) g_invf[j] = (float)(1.0 / pow(10000.0, (double)j / 32.0));
}

// cos/sin of the fp32 angle: double RANGE-REDUCTION only (no fp64 transcendentals),
// then fp32 sincosf on |r| <= pi (fast path, ~2ulp).
__global__ void rope_table_k(const int* __restrict__ startp) {
    int i = blockIdx.x * blockDim.x + threadIdx.x;
    if (i >= L_ * 32) return;
    int pos = *startp + (i >> 5);
    int j = i & 31;
    float ang = (float)pos * g_invf[j];          // fp32 multiply, matches reference
    double td = (double)ang;
    double kd = rint(td * 0.15915494309189535);  // 1/(2*pi)
    float r = (float)(td - kd * 6.283185307179586);
    float s, c;
    sincosf(r, &s, &c);
    g_cos[i] = c;
    g_sin[i] = s;
}

// ---------------- helpers ----------------
__device__ __forceinline__ uint32_t smem_u32(const void* p) {
    uint32_t a;
    asm("{ .reg .u64 t; cvta.to.shared.u64 t, %1; cvt.u32.u64 %0, t; }" : "=r"(a) : "l"(p));
    return a;
}
__device__ __forceinline__ float ex2f(float x) {
    float y; asm("ex2.approx.ftz.f32 %0, %1;" : "=f"(y) : "f"(x)); return y;
}
__device__ __forceinline__ void lds64(uint32_t& x, uint32_t& y, uint32_t a) {
    asm volatile("ld.shared.v2.b32 {%0,%1}, [%2];" : "=r"(x), "=r"(y) : "r"(a));
}
__device__ __forceinline__ void cpa16(uint32_t s, const uint64_t* g) {
    asm volatile("cp.async.cg.shared.global [%0], [%1], 16;" :: "r"(s), "l"(g));
}
#define CP_COMMIT() asm volatile("cp.async.commit_group;" ::: "memory")
#define CP_WAIT0()  asm volatile("cp.async.wait_group 0;" ::: "memory")
__device__ __forceinline__ void mma_f16(float* c, const uint32_t* a, uint32_t b0, uint32_t b1) {
    asm volatile(
        "mma.sync.aligned.m16n8k16.row.col.f32.f16.f16.f32 "
        "{%0,%1,%2,%3}, {%4,%5,%6,%7}, {%8,%9}, {%0,%1,%2,%3};"
        : "+f"(c[0]), "+f"(c[1]), "+f"(c[2]), "+f"(c[3])
        : "r"(a[0]), "r"(a[1]), "r"(a[2]), "r"(a[3]), "r"(b0), "r"(b1));
}
__device__ __forceinline__ uint32_t pack_h(float x0, float x1) {
    __half2 h = __floats2half2_rn(x0, x1);
    return *reinterpret_cast<uint32_t*>(&h);
}
__device__ __forceinline__ void pack_hilo_h(float x0, float x1, uint32_t& hi, uint32_t& lo) {
    __half2 h = __floats2half2_rn(x0, x1);
    float2 hf = __half22float2(h);
    __half2 l = __floats2half2_rn(x0 - hf.x, x1 - hf.y);
    hi = *reinterpret_cast<uint32_t*>(&h);
    lo = *reinterpret_cast<uint32_t*>(&l);
}

// ---------------- fused prep: K -> RoPE'd fp16 hi/lo frags; V -> transposed fp16 frags --
__global__ void __launch_bounds__(256) prep_kv(const float* __restrict__ k,
                                               const float* __restrict__ v) {
    __shared__ float tile[64][65];
    if (blockIdx.x < 8192) {
        // ----- K part -----
        uint32_t g = blockIdx.x * 256 + threadIdx.x;
        int lb = g & 3, la = (g >> 2) & 7, t01 = (g >> 5) & 1, m = (g >> 6) & 1023;
        int sc = g >> 16;
        int b = sc >> 4, h = sc & 15;
        int l = 8 * m + la;
        const float* gk = k + (((long)b * L_ + l) * H_ + h) * D_;
        int d0 = 16 * t01 + 2 * lb;
        float2 x0 = *(const float2*)(gk + d0);
        float2 x1 = *(const float2*)(gk + d0 + 8);
        float2 y0 = *(const float2*)(gk + d0 + 32);
        float2 y1 = *(const float2*)(gk + d0 + 40);
        float2 c0 = *(const float2*)(g_cos + l * 32 + d0);
        float2 c1 = *(const float2*)(g_cos + l * 32 + d0 + 8);
        float2 s0 = *(const float2*)(g_sin + l * 32 + d0);
        float2 s1 = *(const float2*)(g_sin + l * 32 + d0 + 8);
        uint32_t hA, lA, hB, lB;
        pack_hilo_h(x0.x*c0.x - y0.x*s0.x, x0.y*c0.y - y0.y*s0.y, hA, lA);
        pack_hilo_h(x1.x*c1.x - y1.x*s1.x, x1.y*c1.y - y1.y*s1.y, hB, lB);
        uint64_t loHi = (uint64_t)hA | ((uint64_t)hB << 32);
        uint64_t loLo = (uint64_t)lA | ((uint64_t)lB << 32);
        pack_hilo_h(y0.x*c0.x + x0.x*s0.x, y0.y*c0.y + x0.y*s0.y, hA, lA);
        pack_hilo_h(y1.x*c1.x + x1.x*s1.x, y1.y*c1.y + x1.y*s1.y, hB, lB);
        uint64_t hiHi = (uint64_t)hA | ((uint64_t)hB << 32);
        uint64_t hiLo = (uint64_t)lA | ((uint64_t)lB << 32);
        uint32_t base = ((uint32_t)sc * 1024 + m) * 128 + la * 4 + lb;
        g_KfH[base + t01 * 32]       = loHi;
        g_KfL[base + t01 * 32]       = loLo;
        g_KfH[base + (t01 + 2) * 32] = hiHi;
        g_KfL[base + (t01 + 2) * 32] = hiLo;
    } else {
        // ----- V part (smem transpose; scalar smem stores: 65-f rows not 16B aligned) ----
        const int blk = blockIdx.x - 8192;       // sc*128 + gt
        const int sc = blk >> 7, gt = blk & 127;
        const int b = sc >> 4, h = sc & 15;
        const int t = threadIdx.x;
        {
            const int r = t >> 2, dseg = (t & 3) * 16;
            const float* gv = v + (((long)b * L_ + (gt * 64 + r)) * H_ + h) * D_ + dseg;
            float a0[4], a1[4], a2[4], a3[4];
            *(float4*)a0 = *(const float4*)(gv);
            *(float4*)a1 = *(const float4*)(gv + 4);
            *(float4*)a2 = *(const float4*)(gv + 8);
            *(float4*)a3 = *(const float4*)(gv + 12);
            #pragma unroll
            for (int i = 0; i < 4; i++) {
                tile[r][dseg + i]      = a0[i];
                tile[r][dseg + 4 + i]  = a1[i];
                tile[r][dseg + 8 + i]  = a2[i];
                tile[r][dseg + 12 + i] = a3[i];
            }
        }
        __syncthreads();
        const int lb = t & 3, d = (t >> 2) & 63;
        uint64_t* outp = g_Vf + ((uint32_t)(sc * 128 + gt)) * 1024 + d * 4 + lb;
        #pragma unroll
        for (int t2 = 0; t2 < 4; t2++) {
            int r0 = t2 * 16 + 2 * lb;
            uint32_t w0 = pack_h(tile[r0][d],     tile[r0 + 1][d]);
            uint32_t w1 = pack_h(tile[r0 + 8][d], tile[r0 + 9][d]);
            outp[t2 * 256] = (uint64_t)w0 | ((uint64_t)w1 << 32);
        }
    }
}

// smem per buffer: KH 8KB | KL 8KB | V 8KB = 24KB; double buffered = 48KB
#define BUFB 24576
#define P_KH 0
#define P_KL 8192
#define P_V  16384

// ---------------- main: 4 warps, M=32/warp, fp16 4-pass, running max ----------------
__global__ void __launch_bounds__(128, 2)
attn_k(const float* __restrict__ q, float* __restrict__ out) {
    extern __shared__ __align__(16) char smc[];
    const uint32_t sb = smem_u32(smc);
    const int tid = threadIdx.x, w = tid >> 5, lane = tid & 31;
    const int qt = 7 - blockIdx.x;            // heavy CTAs first
    const int n  = blockIdx.y >> 4, h = blockIdx.y & 15, b = blockIdx.z;
    const int sc = b * 16 + h;
    const int qbase = qt * 128;
    const int la = lane >> 2, lb = lane & 3;
    const int nkt = 2 * qt + 2;

    const uint64_t* pKH = g_KfH + ((uint32_t)sc * 1024 + n * 128) * 128;
    const uint64_t* pKL = g_KfL + ((uint32_t)sc * 1024 + n * 128) * 128;
    const uint64_t* pV  = g_Vf  + ((uint32_t)sc * 128  + n * 16 ) * 1024;

    // kick off copy of tile 0
    {
        uint32_t dst = sb + tid * 16;
        const uint32_t o2 = (uint32_t)tid * 2;
        #pragma unroll
        for (int i = 0; i < 4; i++) {
            cpa16(dst + P_KH + i * 2048, pKH + o2 + i * 256);
            cpa16(dst + P_KL + i * 2048, pKL + o2 + i * 256);
            cpa16(dst + P_V  + i * 2048, pV  + o2 + i * 256);
        }
        CP_COMMIT();
    }

    // ---------- Q: load + RoPE(+log2e) + fp16 split -> A fragments (M=32) ----------
    uint32_t Qhi[4][2][4], Qlo[4][2][4];
    {
        const int bq = lb * 2;
        float rot[4][4][4];
        #pragma unroll
        for (int r = 0; r < 4; r++) {
            int m  = 32 * w + la + 8 * r;
            int lq = n * C_ + qbase + m;
            const float* gq = q + (((long)b * L_ + lq) * H_ + h) * D_;
            const float* gc = g_cos + lq * 32;
            const float* gs = g_sin + lq * 32;
            float xv[4][4], cs[2][4], sn[2][4];
            #pragma unroll
            for (int t = 0; t < 4; t++) {
                float2 u0 = *(const float2*)(gq + 16 * t + bq);
                float2 u1 = *(const float2*)(gq + 16 * t + bq + 8);
                xv[t][0] = u0.x; xv[t][1] = u0.y; xv[t][2] = u1.x; xv[t][3] = u1.y;
            }
            #pragma unroll
            for (int t = 0; t < 2; t++) {
                float2 c0 = *(const float2*)(gc + 16 * t + bq);
                float2 c1 = *(const float2*)(gc + 16 * t + bq + 8);
                cs[t][0] = c0.x; cs[t][1] = c0.y; cs[t][2] = c1.x; cs[t][3] = c1.y;
                float2 s0 = *(const float2*)(gs + 16 * t + bq);
                float2 s1 = *(const float2*)(gs + 16 * t + bq + 8);
                sn[t][0] = s0.x; sn[t][1] = s0.y; sn[t][2] = s1.x; sn[t][3] = s1.y;
            }
            #pragma unroll
            for (int t = 0; t < 2; t++)
                #pragma unroll
                for (int i = 0; i < 4; i++) {
                    rot[r][t][i]   = (xv[t][i] * cs[t][i] - xv[t+2][i] * sn[t][i]) * LOG2E;
                    rot[r][t+2][i] = (xv[t+2][i] * cs[t][i] + xv[t][i] * sn[t][i]) * LOG2E;
                }
        }
        #pragma unroll
        for (int mt = 0; mt < 2; mt++)
            #pragma unroll
            for (int t = 0; t < 4; t++) {
                pack_hilo_h(rot[2*mt  ][t][0], rot[2*mt  ][t][1], Qhi[t][mt][0], Qlo[t][mt][0]);
                pack_hilo_h(rot[2*mt+1][t][0], rot[2*mt+1][t][1], Qhi[t][mt][1], Qlo[t][mt][1]);
                pack_hilo_h(rot[2*mt  ][t][2], rot[2*mt  ][t][3], Qhi[t][mt][2], Qlo[t][mt][2]);
                pack_hilo_h(rot[2*mt+1][t][2], rot[2*mt+1][t][3], Qhi[t][mt][3], Qlo[t][mt][3]);
            }
    }

    float o[2][8][4];
    #pragma unroll
    for (int mt = 0; mt < 2; mt++)
        #pragma unroll
        for (int j = 0; j < 8; j++)
            #pragma unroll
            for (int i = 0; i < 4; i++) o[mt][j][i] = 0.f;
    float ls[2][2] = {{0.f, 0.f}, {0.f, 0.f}};
    float m_[2][2] = {{-1e30f, -1e30f}, {-1e30f, -1e30f}};

    const int rowA0 = qbase + 32 * w + la;
    const int rowA1 = rowA0 + 8;
    const int rowB0 = rowA0 + 16;
    const int rowB1 = rowA0 + 24;

    for (int kt = 0; kt < nkt; kt++) {
        const int kbase = kt * BK;
        CP_WAIT0();
        __syncthreads();
        if (kt + 1 < nkt) {
            uint32_t dst = sb + ((kt + 1) & 1) * BUFB + tid * 16;
            const uint32_t o2 = (uint32_t)(kt + 1) * 1024 + (uint32_t)tid * 2;
            #pragma unroll
            for (int i = 0; i < 4; i++) {
                cpa16(dst + P_KH + i * 2048, pKH + o2 + i * 256);
                cpa16(dst + P_KL + i * 2048, pKL + o2 + i * 256);
                cpa16(dst + P_V  + i * 2048, pV  + o2 + i * 256);
            }
            CP_COMMIT();
        }
        const uint32_t KB = sb + (kt & 1) * BUFB;
        const uint32_t fo = (uint32_t)(la * 32 + lb * 8);

        // ---------- S = Q @ K^T (3-pass fp16 split, j-pair interleaved) ----------
        float c[2][8][4];
        #pragma unroll
        for (int mt = 0; mt < 2; mt++)
            #pragma unroll
            for (int j = 0; j < 8; j++)
                #pragma unroll
                for (int i = 0; i < 4; i++) c[mt][j][i] = 0.f;

        #pragma unroll
        for (int t = 0; t < 4; t++) {
            #pragma unroll
            for (int j = 0; j < 8; j += 2) {
                uint32_t a0 = KB + P_KH + (uint32_t)j * 1024 + (uint32_t)t * 256 + fo;
                uint32_t bh0a, bh1a, bh0b, bh1b, bl0a, bl1a, bl0b, bl1b;
                lds64(bh0a, bh1a, a0);
                lds64(bh0b, bh1b, a0 + 1024);
                lds64(bl0a, bl1a, a0 + (P_KL - P_KH));
                lds64(bl0b, bl1b, a0 + (P_KL - P_KH) + 1024);
                mma_f16(c[0][j],   Qhi[t][0], bh0a, bh1a);
                mma_f16(c[0][j+1], Qhi[t][0], bh0b, bh1b);
                mma_f16(c[1][j],   Qhi[t][1], bh0a, bh1a);
                mma_f16(c[1][j+1], Qhi[t][1], bh0b, bh1b);
                mma_f16(c[0][j],   Qlo[t][0], bh0a, bh1a);
                mma_f16(c[0][j+1], Qlo[t][0], bh0b, bh1b);
                mma_f16(c[1][j],   Qlo[t][1], bh0a, bh1a);
                mma_f16(c[1][j+1], Qlo[t][1], bh0b, bh1b);
                mma_f16(c[0][j],   Qhi[t][0], bl0a, bl1a);
                mma_f16(c[0][j+1], Qhi[t][0], bl0b, bl1b);
                mma_f16(c[1][j],   Qhi[t][1], bl0a, bl1a);
                mma_f16(c[1][j+1], Qhi[t][1], bl0b, bl1b);
            }
        }

        // ---------- mask ----------
        if (kbase + BK > rowA0) {
            #pragma unroll
            for (int j = 0; j < 8; j++) {
                int col = kbase + 8 * j + lb * 2;
                if (col     > rowA0) c[0][j][0] = -1e30f;
                if (col + 1 > rowA0) c[0][j][1] = -1e30f;
                if (col     > rowA1) c[0][j][2] = -1e30f;
                if (col + 1 > rowA1) c[0][j][3] = -1e30f;
                if (col     > rowB0) c[1][j][0] = -1e30f;
                if (col + 1 > rowB0) c[1][j][1] = -1e30f;
                if (col     > rowB1) c[1][j][2] = -1e30f;
                if (col + 1 > rowB1) c[1][j][3] = -1e30f;
            }
        }

        // ---------- running max update + ls rescale ----------
        float scl[2][2];
        #pragma unroll
        for (int mt = 0; mt < 2; mt++)
            #pragma unroll
            for (int rh = 0; rh < 2; rh++) {
                float mx = -1e30f;
                #pragma unroll
                for (int j = 0; j < 8; j++)
                    mx = fmaxf(mx, fmaxf(c[mt][j][2*rh], c[mt][j][2*rh+1]));
                mx = fmaxf(mx, __shfl_xor_sync(0xffffffffu, mx, 1));
                mx = fmaxf(mx, __shfl_xor_sync(0xffffffffu, mx, 2));
                float mn = fmaxf(m_[mt][rh], mx);
                float s = ex2f(m_[mt][rh] - mn);
                m_[mt][rh] = mn;
                scl[mt][rh] = s;
                ls[mt][rh] *= s;
            }
        // O rescale only when some row's max moved (vote; late tiles mostly skip)
        bool need = (scl[0][0] != 1.f) | (scl[0][1] != 1.f) |
                    (scl[1][0] != 1.f) | (scl[1][1] != 1.f);
        if (__any_sync(0xffffffffu, need)) {
            #pragma unroll
            for (int mt = 0; mt < 2; mt++)
                #pragma unroll
                for (int j = 0; j < 8; j++) {
                    o[mt][j][0] *= scl[mt][0]; o[mt][j][1] *= scl[mt][0];
                    o[mt][j][2] *= scl[mt][1]; o[mt][j][3] *= scl[mt][1];
                }
        }

        // ---------- exp2 + pack P (single fp16 plane, in [0,1]) ----------
        uint32_t Phi[2][4][4];
        #pragma unroll
        for (int j = 0; j < 8; j++) {
            float pA0 = ex2f(c[0][j][0] - m_[0][0]);
            float pA1 = ex2f(c[0][j][1] - m_[0][0]);
            float pA2 = ex2f(c[0][j][2] - m_[0][1]);
            float pA3 = ex2f(c[0][j][3] - m_[0][1]);
            float pB0 = ex2f(c[1][j][0] - m_[1][0]);
            float pB1 = ex2f(c[1][j][1] - m_[1][0]);
            float pB2 = ex2f(c[1][j][2] - m_[1][1]);
            float pB3 = ex2f(c[1][j][3] - m_[1][1]);
            ls[0][0] += pA0 + pA1; ls[0][1] += pA2 + pA3;
            ls[1][0] += pB0 + pB1; ls[1][1] += pB2 + pB3;
            int t = j >> 1, off = (j & 1) ? 2 : 0;
            Phi[0][t][off]     = pack_h(pA0, pA1);
            Phi[0][t][off + 1] = pack_h(pA2, pA3);
            Phi[1][t][off]     = pack_h(pB0, pB1);
            Phi[1][t][off + 1] = pack_h(pB2, pB3);
        }

        // ---------- O += P @ V (single pass, j-pair interleaved) ----------
        #pragma unroll
        for (int t = 0; t < 4; t++) {
            #pragma unroll
            for (int j = 0; j < 8; j += 2) {
                uint32_t a0 = KB + P_V + (uint32_t)t * 2048 + (uint32_t)j * 256 + fo;
                uint32_t va0, va1, vb0, vb1;
                lds64(va0, va1, a0);
                lds64(vb0, vb1, a0 + 256);
                mma_f16(o[0][j],   Phi[0][t], va0, va1);
                mma_f16(o[0][j+1], Phi[0][t], vb0, vb1);
                mma_f16(o[1][j],   Phi[1][t], va0, va1);
                mma_f16(o[1][j+1], Phi[1][t], vb0, vb1);
            }
        }
    }

    // ---------- normalize + store ----------
    #pragma unroll
    for (int mt = 0; mt < 2; mt++)
        #pragma unroll
        for (int i = 0; i < 2; i++) {
            ls[mt][i] += __shfl_xor_sync(0xffffffffu, ls[mt][i], 1);
            ls[mt][i] += __shfl_xor_sync(0xffffffffu, ls[mt][i], 2);
        }
    #pragma unroll
    for (int mt = 0; mt < 2; mt++) {
        float inv0 = 1.0f / ls[mt][0], inv1 = 1.0f / ls[mt][1];
        int r0 = qbase + 32 * w + 16 * mt + la;
        const int lq0 = n * C_ + r0, lq1 = lq0 + 8;
        float* g0 = out + (((long)b * L_ + lq0) * H_ + h) * D_;
        float* g1 = out + (((long)b * L_ + lq1) * H_ + h) * D_;
        #pragma unroll
        for (int j = 0; j < 8; j++) {
            int d = 8 * j + lb * 2;
            *(float2*)(g0 + d) = make_float2(o[mt][j][0] * inv0, o[mt][j][1] * inv0);
            *(float2*)(g1 + d) = make_float2(o[mt][j][2] * inv1, o[mt][j][3] * inv1);
        }
    }
}

extern "C" void kernel_launch(void* const* d_in, const int* in_sizes, int n_in,
                              void* d_out, int out_size) {
    const float* q = (const float*)d_in[0];
    const float* k = (const float*)d_in[1];
    const float* v = (const float*)d_in[2];
    const int* st  = (const int*)d_in[3];
    float* out     = (float*)d_out;

    cudaFuncSetAttribute(attn_k, cudaFuncAttributeMaxDynamicSharedMemorySize, 2 * BUFB);

    invf_k<<<1, 32>>>();
    rope_table_k<<<(L_ * 32 + 255) / 256, 256>>>(st);
    prep_kv<<<8192 + 4096, 256>>>(k, v);
    attn_k<<<dim3(8, (L_ / C_) * H_, B_), 128, 2 * BUFB>>>(q, out);
}